// round 13
// baseline (speedup 1.0000x reference)
#include <cuda_runtime.h>
#include <float.h>
#include <math.h>

#define NB 16
#define NP 1024
#define NC 91
#define MAX_DET 100
#define SCORE_THRESH 0.05f
#define NMS_THRESH 0.5f
#define BBOX_CLIP 4.135166556742356f  /* log(1000/16) */
#define BK 128                        /* bucket capacity per (image,class) */
#define LOG2E 1.4426950408889634f

#define C_PARTS 32                    /* 32 entries per part-CTA */

// ---------------- scratch (no allocations allowed) ----------------
__device__ float  g_scores[NB * NP];
__device__ int    g_labels[NB * NP];           // 0 if invalid, else 1..90
__device__ float4 g_boxes[NB * NP];

__device__ int    g_bcnt[NB * 91];             // bucket counts   (reset by B owner-warps)
__device__ float4 g_bbox[NB * 91 * BK];        // bucket boxes (raw clipped)
__device__ float  g_bsc [NB * 91 * BK];        // bucket scores
__device__ int    g_bidx[NB * 91 * BK];        // bucket original idx (0..1023)
__device__ int    g_maxc[NB];                  // per-image max coord (reset by C)
__device__ int    g_M[NB];                     // kept count per image (reset by A)
__device__ unsigned long long g_klist[NB * NP];// kept keys per image (contiguous)

// monotone injective float <-> ordinal-uint maps
__device__ __forceinline__ unsigned f2ord(float x) {
    unsigned u = __float_as_uint(x);
    return (u & 0x80000000u) ? ~u : (u | 0x80000000u);
}
__device__ __forceinline__ float ord2f(unsigned u) {
    return __uint_as_float((u & 0x80000000u) ? (u ^ 0x80000000u) : ~u);
}

// softmax-term exp: one MUFU.EX2 + one FMUL (no software expf wrapper)
__device__ __forceinline__ float exp_fast(float x) {
    return exp2f(x * LOG2E);
}

// ---------------- Kernel A: softmax-max/argmax + decode + clip + bucket ------
// One warp per TWO proposals (2k, 2k+1 — always same image). Single wave.
__global__ void score_decode_kernel(const float* __restrict__ logits,
                                    const float* __restrict__ deltas,
                                    const float* __restrict__ props,
                                    const int*   __restrict__ imsz) {
    if (blockIdx.x == 0 && threadIdx.x < NB) g_M[threadIdx.x] = 0;

    const int warpid = (blockIdx.x * blockDim.x + threadIdx.x) >> 5;
    const int lane   = threadIdx.x & 31;
    const int pa     = warpid * 2;                 // first proposal of the pair
    if (pa >= NB * NP) return;
    const int b = pa / NP;                         // pa, pa+1 share the image

    // hoisted loads independent of the logits (lanes 0/1 own proposals a/b)
    float4 pr;
    int ih = 0, iw = 0;
    const int myP = pa + lane;
    if (lane < 2) {
        pr = *reinterpret_cast<const float4*>(props + (size_t)myP * 4);
        ih = imsz[b * 2 + 0];
        iw = imsz[b * 2 + 1];
    }

    // 6 logit loads up-front (MLP 6)
    const float* rowa = logits + (size_t)pa * NC;
    const float* rowb = rowa + NC;
    const bool has2 = (lane < NC - 64);            // lane < 27
    float la0 = rowa[lane], la1 = rowa[lane + 32];
    float lb0 = rowb[lane], lb1 = rowb[lane + 32];
    float la2 = has2 ? rowa[lane + 64] : -FLT_MAX;
    float lb2 = has2 ? rowb[lane + 64] : -FLT_MAX;

    // lane-local argmax (ascending index order + strict > = first-index tiebreak)
    unsigned ua = f2ord(la0); int bia = lane;
    { unsigned u = f2ord(la1); if (u > ua) { ua = u; bia = lane + 32; }
      u = f2ord(la2);          if (u > ua) { ua = u; bia = lane + 64; } }
    unsigned ub = f2ord(lb0); int bib = lane;
    { unsigned u = f2ord(lb1); if (u > ub) { ub = u; bib = lane + 32; }
      u = f2ord(lb2);          if (u > ub) { ub = u; bib = lane + 64; } }

    // warp argmax via REDUX (max value, then min index among achievers)
    unsigned uam = __reduce_max_sync(0xffffffffu, ua);
    unsigned ubm = __reduce_max_sync(0xffffffffu, ub);
    int biA = (int)__reduce_min_sync(0xffffffffu, (ua == uam) ? (unsigned)bia : 0x7fffffffu);
    int biB = (int)__reduce_min_sync(0xffffffffu, (ub == ubm) ? (unsigned)bib : 0x7fffffffu);
    float bvA = ord2f(uam);
    float bvB = ord2f(ubm);

    // softmax denominators: bare EX2 path (exp_fast), butterfly reduce
    float sa = exp_fast(la0 - bvA) + exp_fast(la1 - bvA) + (has2 ? exp_fast(la2 - bvA) : 0.0f);
    float sb = exp_fast(lb0 - bvB) + exp_fast(lb1 - bvB) + (has2 ? exp_fast(lb2 - bvB) : 0.0f);
    #pragma unroll
    for (int o = 16; o; o >>= 1) {
        sa += __shfl_xor_sync(0xffffffffu, sa, o);
        sb += __shfl_xor_sync(0xffffffffu, sb, o);
    }
    sa = __shfl_sync(0xffffffffu, sa, 0);
    sb = __shfl_sync(0xffffffffu, sb, 0);

    // decode: lane 0 handles proposal a, lane 1 handles proposal b (concurrent)
    if (lane < 2) {
        float score = 1.0f / ((lane == 0) ? sa : sb);
        int   label = (lane == 0) ? biA : biB;
        int   valid = (label > 0) && (score > SCORE_THRESH);

        float x1 = pr.x, y1 = pr.y, x2 = pr.z, y2 = pr.w;
        float w = x2 - x1, h = y2 - y1;
        float cx = x1 + 0.5f * w, cy = y1 + 0.5f * h;

        const float* dd = deltas + (size_t)myP * (NC * 4) + 4 * label;
        float dx = dd[0], dy = dd[1];
        float dw = fminf(dd[2], BBOX_CLIP), dh = fminf(dd[3], BBOX_CLIP);
        float pcx = dx * w + cx, pcy = dy * h + cy;
        float pw = expf(dw) * w, ph = expf(dh) * h;
        float bx1 = pcx - 0.5f * pw, by1 = pcy - 0.5f * ph;
        float bx2 = pcx + 0.5f * pw, by2 = pcy + 0.5f * ph;

        float hb = (float)ih;
        float wb = (float)iw;
        bx1 = fminf(fmaxf(bx1, 0.0f), wb);
        by1 = fminf(fmaxf(by1, 0.0f), hb);
        bx2 = fminf(fmaxf(bx2, 0.0f), wb);
        by2 = fminf(fmaxf(by2, 0.0f), hb);

        g_boxes[myP]  = make_float4(bx1, by1, bx2, by2);
        g_scores[myP] = score;
        g_labels[myP] = valid ? label : 0;

        if (valid) {
            // exact max over valid box coords (all >= 0, float bits monotone)
            float mc = fmaxf(fmaxf(bx1, by1), fmaxf(bx2, by2));
            atomicMax(&g_maxc[b], __float_as_int(mc));
            int bc = b * 91 + label;
            int p2 = atomicAdd(&g_bcnt[bc], 1);
            if (p2 < BK) {
                int slot = bc * BK + p2;
                g_bbox[slot] = make_float4(bx1, by1, bx2, by2);
                g_bsc[slot]  = score;
                g_bidx[slot] = myP - b * NP;
            }
        }
    }
}

// ---------------- Kernel B: NMS, one warp per (image, class), registers only ----
// Kept keys appended to the image's contiguous list with ONE atomic per warp.
// Each warp resets its own g_bcnt[bc] after reading it (sole owner).
__global__ __launch_bounds__(256) void nms_class_kernel() {
    int gwarp = (blockIdx.x * blockDim.x + threadIdx.x) >> 5;
    int lane  = threadIdx.x & 31;
    if (gwarp >= NB * 90) return;
    int b = gwarp / 90;
    int c = 1 + gwarp % 90;
    int bc = b * 91 + c;

    int n = g_bcnt[bc];
    __syncwarp();
    if (lane == 0 && n != 0) g_bcnt[bc] = 0;   // reset for next replay
    if (n > BK) n = BK;
    if (n == 0) return;

    float K   = __int_as_float(g_maxc[b]) + 1.0f;
    float off = (float)c * K;    // label * (max_coord + 1), reference FP order

    float4 bxs[4]; float scs[4]; int idxs[4];
    unsigned alive = 0;
    #pragma unroll
    for (int j = 0; j < 4; ++j) {
        int e = j * 32 + lane;
        if (e < n) {
            float4 v = g_bbox[bc * BK + e];
            bxs[j] = make_float4(v.x + off, v.y + off, v.z + off, v.w + off);
            scs[j] = g_bsc[bc * BK + e];
            idxs[j] = g_bidx[bc * BK + e];
            alive |= (1u << j);
        } else {
            bxs[j] = make_float4(0.f, 0.f, 0.f, 0.f);
            scs[j] = 0.f; idxs[j] = 0;
        }
    }

    unsigned keptm = 0;
    while (true) {
        unsigned long long best = ~0ULL;
        #pragma unroll
        for (int j = 0; j < 4; ++j) {
            if (alive & (1u << j)) {
                unsigned long long k =
                    ((unsigned long long)(~__float_as_uint(scs[j])) << 20) |
                    ((unsigned long long)(unsigned)idxs[j] << 10) |
                    (unsigned long long)(unsigned)(j * 32 + lane);
                if (k < best) best = k;
            }
        }
        #pragma unroll
        for (int o = 16; o; o >>= 1) {
            unsigned long long ob = __shfl_xor_sync(0xffffffffu, best, o);
            if (ob < best) best = ob;
        }
        if (best == ~0ULL) break;

        int e   = (int)(best & 1023ULL);
        int js  = e >> 5;
        int src = e & 31;
        float4 own = (js == 0) ? bxs[0] : (js == 1) ? bxs[1] : (js == 2) ? bxs[2] : bxs[3];
        float4 A;
        A.x = __shfl_sync(0xffffffffu, own.x, src);
        A.y = __shfl_sync(0xffffffffu, own.y, src);
        A.z = __shfl_sync(0xffffffffu, own.z, src);
        A.w = __shfl_sync(0xffffffffu, own.w, src);
        if (lane == src) {
            alive &= ~(1u << js);
            keptm |= (1u << js);
        }
        float areaA = (A.z - A.x) * (A.w - A.y);

        #pragma unroll
        for (int j = 0; j < 4; ++j) {
            if (alive & (1u << j)) {
                float4 Bx = bxs[j];
                float areaB = (Bx.z - Bx.x) * (Bx.w - Bx.y);
                float ltx = fmaxf(A.x, Bx.x), lty = fmaxf(A.y, Bx.y);
                float rbx = fminf(A.z, Bx.z), rby = fminf(A.w, Bx.w);
                float wx = fmaxf(rbx - ltx, 0.0f), wy = fmaxf(rby - lty, 0.0f);
                float inter = wx * wy;
                float iou = inter / (areaA + areaB - inter + 1e-9f);
                if (iou > NMS_THRESH) alive &= ~(1u << j);
            }
        }
    }

    // single aggregated atomic per warp, ballot-prefixed positions
    int pref[4];
    int kc = 0;
    #pragma unroll
    for (int j = 0; j < 4; ++j) {
        bool kept = (keptm >> j) & 1u;
        unsigned bal = __ballot_sync(0xffffffffu, kept);
        pref[j] = kc + __popc(bal & ((1u << lane) - 1u));
        kc += __popc(bal);
    }
    int basep = 0;
    if (lane == 0 && kc > 0) basep = atomicAdd(&g_M[b], kc);
    basep = __shfl_sync(0xffffffffu, basep, 0);
    #pragma unroll
    for (int j = 0; j < 4; ++j) {
        if ((keptm >> j) & 1u) {
            g_klist[b * NP + basep + pref[j]] =
                ((unsigned long long)(~__float_as_uint(scs[j])) << 10) |
                (unsigned long long)(unsigned)idxs[j];
        }
    }
}

// ---------------- Kernel C: top-100 rank counting, 4 entries per warp --------
// grid = NB * C_PARTS CTAs of 256 threads; no smem, no barriers.
__global__ __launch_bounds__(256) void topk_rank_kernel(float* __restrict__ out) {
    if (blockIdx.x == 0 && threadIdx.x < NB) g_maxc[threadIdx.x] = 0;

    const int img  = blockIdx.x / C_PARTS;
    const int part = blockIdx.x % C_PARTS;
    const int t    = threadIdx.x;
    const int warp = t >> 5;
    const int lane = t & 31;

    int M = g_M[img];
    if (M > NP) M = NP;

    float* boxes_out  = out;
    float* scores_out = out + NB * MAX_DET * 4;
    float* labels_out = out + NB * MAX_DET * 5;

    // default fill (part 0 only)
    const int filled = M < MAX_DET ? M : MAX_DET;
    if (part == 0 && t >= filled && t < MAX_DET) {
        int base = img * MAX_DET + t;
        boxes_out[base * 4 + 0] = 0.0f;
        boxes_out[base * 4 + 1] = 0.0f;
        boxes_out[base * 4 + 2] = 0.0f;
        boxes_out[base * 4 + 3] = 0.0f;
        scores_out[base] = 0.0f;
        labels_out[base] = -1.0f;
    }

    const unsigned long long* keys = g_klist + (size_t)img * NP;
    const int e0 = part * 32 + warp * 4;
    if (e0 >= M) return;

    // broadcast-load up to 4 entry keys (valid keys are always < ~0ULL)
    unsigned long long k0 = (e0 + 0 < M) ? __ldg(keys + e0 + 0) : ~0ULL;
    unsigned long long k1 = (e0 + 1 < M) ? __ldg(keys + e0 + 1) : ~0ULL;
    unsigned long long k2 = (e0 + 2 < M) ? __ldg(keys + e0 + 2) : ~0ULL;
    unsigned long long k3 = (e0 + 3 < M) ? __ldg(keys + e0 + 3) : ~0ULL;

    int r0 = 0, r1 = 0, r2 = 0, r3 = 0;
    #pragma unroll 4
    for (int j = lane; j < M; j += 32) {
        unsigned long long kj = __ldg(keys + j);
        r0 += (kj < k0);
        r1 += (kj < k1);
        r2 += (kj < k2);
        r3 += (kj < k3);
    }
    #pragma unroll
    for (int o = 16; o; o >>= 1) {
        r0 += __shfl_xor_sync(0xffffffffu, r0, o);
        r1 += __shfl_xor_sync(0xffffffffu, r1, o);
        r2 += __shfl_xor_sync(0xffffffffu, r2, o);
        r3 += __shfl_xor_sync(0xffffffffu, r3, o);
    }

    if (lane == 0) {
        unsigned long long ks[4] = {k0, k1, k2, k3};
        int rs[4] = {r0, r1, r2, r3};
        #pragma unroll
        for (int i = 0; i < 4; ++i) {
            if (e0 + i < M && rs[i] < MAX_DET) {
                int idx = (int)(ks[i] & 1023ULL);
                int g = img * NP + idx;
                float4 v = g_boxes[g];
                int base = img * MAX_DET + rs[i];
                boxes_out[base * 4 + 0] = v.x;
                boxes_out[base * 4 + 1] = v.y;
                boxes_out[base * 4 + 2] = v.z;
                boxes_out[base * 4 + 3] = v.w;
                scores_out[base] = g_scores[g];
                labels_out[base] = (float)g_labels[g];
            }
        }
    }
}

// ---------------- launch ----------------
extern "C" void kernel_launch(void* const* d_in, const int* in_sizes, int n_in,
                              void* d_out, int out_size) {
    const float* class_logits  = (const float*)d_in[0];
    const float* bbox_deltas   = (const float*)d_in[1];
    const float* roi_proposals = (const float*)d_in[2];
    const int*   image_sizes   = (const int*)d_in[3];
    float* out = (float*)d_out;

    // A: one warp per 2 proposals -> 8192 warps -> 1024 CTAs of 256 threads
    int warpsA  = (NB * NP) / 2;
    int blocksA = (warpsA * 32) / 256;
    score_decode_kernel<<<blocksA, 256>>>(class_logits, bbox_deltas,
                                          roi_proposals, image_sizes);

    int nmsWarps = NB * 90;
    int nmsBlocks = (nmsWarps * 32 + 255) / 256;
    nms_class_kernel<<<nmsBlocks, 256>>>();

    topk_rank_kernel<<<NB * C_PARTS, 256>>>(out);
}

// round 14
// speedup vs baseline: 1.0420x; 1.0420x over previous
#include <cuda_runtime.h>
#include <float.h>
#include <math.h>

#define NB 16
#define NP 1024
#define NC 91
#define MAX_DET 100
#define SCORE_THRESH 0.05f
#define NMS_THRESH 0.5f
#define BBOX_CLIP 4.135166556742356f  /* log(1000/16) */
#define BK 128                        /* bucket capacity per (image,class) */
#define LOG2E 1.4426950408889634f
#define LN2   0.6931471805599453f

#define C_PARTS 32                    /* 32 entries per part-CTA */

// ---------------- scratch (no allocations allowed) ----------------
__device__ float  g_scores[NB * NP];
__device__ int    g_labels[NB * NP];           // 0 if invalid, else 1..90
__device__ float4 g_boxes[NB * NP];

__device__ int    g_bcnt[NB * 91];             // bucket counts   (reset by B owner-warps)
__device__ float4 g_bbox[NB * 91 * BK];        // bucket boxes (raw clipped)
__device__ float  g_bsc [NB * 91 * BK];        // bucket scores
__device__ int    g_bidx[NB * 91 * BK];        // bucket original idx (0..1023)
__device__ int    g_maxc[NB];                  // per-image max coord (reset by C)
__device__ int    g_M[NB];                     // kept count per image (reset by A)
__device__ unsigned long long g_klist[NB * NP];// kept keys per image (contiguous)

// monotone injective float <-> ordinal-uint maps
__device__ __forceinline__ unsigned f2ord(float x) {
    unsigned u = __float_as_uint(x);
    return (u & 0x80000000u) ? ~u : (u | 0x80000000u);
}
__device__ __forceinline__ float ord2f(unsigned u) {
    return __uint_as_float((u & 0x80000000u) ? (u ^ 0x80000000u) : ~u);
}

// e^x for x <= 0, pure FMA/ALU pipes (no MUFU). Max rel err ~5e-9 + rounding.
__device__ __forceinline__ float exp_poly(float x) {
    float y = x * LOG2E;
    y = fmaxf(y, -126.0f);          // underflow -> 2^-126 * p ~ 0 (harmless in sum)
    float r = rintf(y);             // n = round(y); f = y - n in [-0.5, 0.5]
    float f = y - r;
    float t = f * LN2;              // |t| <= 0.3466
    float p = 1.9841270114e-4f;     // 1/7!
    p = fmaf(p, t, 1.3888888961e-3f);   // 1/6!
    p = fmaf(p, t, 8.3333337680e-3f);   // 1/5!
    p = fmaf(p, t, 4.1666667908e-2f);   // 1/4!
    p = fmaf(p, t, 1.6666667163e-1f);   // 1/3!
    p = fmaf(p, t, 5.0000000000e-1f);   // 1/2!
    p = fmaf(p, t, 1.0f);
    p = fmaf(p, t, 1.0f);
    int n = (int)r;                 // n in [-126, 0]
    return __uint_as_float((unsigned)(n + 127) << 23) * p;   // 2^n * e^t
}

// ---------------- Kernel A: softmax-max/argmax + decode + clip + bucket ------
// One warp per TWO proposals (2k, 2k+1 — always same image). Single wave.
__global__ void score_decode_kernel(const float* __restrict__ logits,
                                    const float* __restrict__ deltas,
                                    const float* __restrict__ props,
                                    const int*   __restrict__ imsz) {
    if (blockIdx.x == 0 && threadIdx.x < NB) g_M[threadIdx.x] = 0;

    const int warpid = (blockIdx.x * blockDim.x + threadIdx.x) >> 5;
    const int lane   = threadIdx.x & 31;
    const int pa     = warpid * 2;                 // first proposal of the pair
    if (pa >= NB * NP) return;
    const int b = pa / NP;                         // pa, pa+1 share the image

    // hoisted loads independent of the logits (lanes 0/1 own proposals a/b)
    float4 pr;
    int ih = 0, iw = 0;
    const int myP = pa + lane;
    if (lane < 2) {
        pr = *reinterpret_cast<const float4*>(props + (size_t)myP * 4);
        ih = imsz[b * 2 + 0];
        iw = imsz[b * 2 + 1];
    }

    // 6 logit loads up-front (MLP 6)
    const float* rowa = logits + (size_t)pa * NC;
    const float* rowb = rowa + NC;
    const bool has2 = (lane < NC - 64);            // lane < 27
    float la0 = rowa[lane], la1 = rowa[lane + 32];
    float lb0 = rowb[lane], lb1 = rowb[lane + 32];
    float la2 = has2 ? rowa[lane + 64] : -FLT_MAX;
    float lb2 = has2 ? rowb[lane + 64] : -FLT_MAX;

    // lane-local argmax (ascending index order + strict > = first-index tiebreak)
    unsigned ua = f2ord(la0); int bia = lane;
    { unsigned u = f2ord(la1); if (u > ua) { ua = u; bia = lane + 32; }
      u = f2ord(la2);          if (u > ua) { ua = u; bia = lane + 64; } }
    unsigned ub = f2ord(lb0); int bib = lane;
    { unsigned u = f2ord(lb1); if (u > ub) { ub = u; bib = lane + 32; }
      u = f2ord(lb2);          if (u > ub) { ub = u; bib = lane + 64; } }

    // warp argmax via REDUX (max value, then min index among achievers)
    unsigned uam = __reduce_max_sync(0xffffffffu, ua);
    unsigned ubm = __reduce_max_sync(0xffffffffu, ub);
    int biA = (int)__reduce_min_sync(0xffffffffu, (ua == uam) ? (unsigned)bia : 0x7fffffffu);
    int biB = (int)__reduce_min_sync(0xffffffffu, (ub == ubm) ? (unsigned)bib : 0x7fffffffu);
    float bvA = ord2f(uam);
    float bvB = ord2f(ubm);

    // softmax denominators: FMA-pipe exp (no MUFU), butterfly reduce
    float sa = exp_poly(la0 - bvA) + exp_poly(la1 - bvA) + (has2 ? exp_poly(la2 - bvA) : 0.0f);
    float sb = exp_poly(lb0 - bvB) + exp_poly(lb1 - bvB) + (has2 ? exp_poly(lb2 - bvB) : 0.0f);
    #pragma unroll
    for (int o = 16; o; o >>= 1) {
        sa += __shfl_xor_sync(0xffffffffu, sa, o);
        sb += __shfl_xor_sync(0xffffffffu, sb, o);
    }
    sa = __shfl_sync(0xffffffffu, sa, 0);
    sb = __shfl_sync(0xffffffffu, sb, 0);

    // decode: lane 0 handles proposal a, lane 1 handles proposal b (concurrent)
    if (lane < 2) {
        float score = 1.0f / ((lane == 0) ? sa : sb);
        int   label = (lane == 0) ? biA : biB;
        int   valid = (label > 0) && (score > SCORE_THRESH);

        float x1 = pr.x, y1 = pr.y, x2 = pr.z, y2 = pr.w;
        float w = x2 - x1, h = y2 - y1;
        float cx = x1 + 0.5f * w, cy = y1 + 0.5f * h;

        const float* dd = deltas + (size_t)myP * (NC * 4) + 4 * label;
        float dx = dd[0], dy = dd[1];
        float dw = fminf(dd[2], BBOX_CLIP), dh = fminf(dd[3], BBOX_CLIP);
        float pcx = dx * w + cx, pcy = dy * h + cy;
        float pw = expf(dw) * w, ph = expf(dh) * h;
        float bx1 = pcx - 0.5f * pw, by1 = pcy - 0.5f * ph;
        float bx2 = pcx + 0.5f * pw, by2 = pcy + 0.5f * ph;

        float hb = (float)ih;
        float wb = (float)iw;
        bx1 = fminf(fmaxf(bx1, 0.0f), wb);
        by1 = fminf(fmaxf(by1, 0.0f), hb);
        bx2 = fminf(fmaxf(bx2, 0.0f), wb);
        by2 = fminf(fmaxf(by2, 0.0f), hb);

        g_boxes[myP]  = make_float4(bx1, by1, bx2, by2);
        g_scores[myP] = score;
        g_labels[myP] = valid ? label : 0;

        if (valid) {
            // exact max over valid box coords (all >= 0, float bits monotone)
            float mc = fmaxf(fmaxf(bx1, by1), fmaxf(bx2, by2));
            atomicMax(&g_maxc[b], __float_as_int(mc));
            int bc = b * 91 + label;
            int p2 = atomicAdd(&g_bcnt[bc], 1);
            if (p2 < BK) {
                int slot = bc * BK + p2;
                g_bbox[slot] = make_float4(bx1, by1, bx2, by2);
                g_bsc[slot]  = score;
                g_bidx[slot] = myP - b * NP;
            }
        }
    }
}

// ---------------- Kernel B: NMS, one warp per (image, class), registers only ----
// Kept keys appended to the image's contiguous list with ONE atomic per warp.
// Each warp resets its own g_bcnt[bc] after reading it (sole owner).
__global__ __launch_bounds__(256) void nms_class_kernel() {
    int gwarp = (blockIdx.x * blockDim.x + threadIdx.x) >> 5;
    int lane  = threadIdx.x & 31;
    if (gwarp >= NB * 90) return;
    int b = gwarp / 90;
    int c = 1 + gwarp % 90;
    int bc = b * 91 + c;

    int n = g_bcnt[bc];
    __syncwarp();
    if (lane == 0 && n != 0) g_bcnt[bc] = 0;   // reset for next replay
    if (n > BK) n = BK;
    if (n == 0) return;

    float K   = __int_as_float(g_maxc[b]) + 1.0f;
    float off = (float)c * K;    // label * (max_coord + 1), reference FP order

    float4 bxs[4]; float scs[4]; int idxs[4];
    unsigned alive = 0;
    #pragma unroll
    for (int j = 0; j < 4; ++j) {
        int e = j * 32 + lane;
        if (e < n) {
            float4 v = g_bbox[bc * BK + e];
            bxs[j] = make_float4(v.x + off, v.y + off, v.z + off, v.w + off);
            scs[j] = g_bsc[bc * BK + e];
            idxs[j] = g_bidx[bc * BK + e];
            alive |= (1u << j);
        } else {
            bxs[j] = make_float4(0.f, 0.f, 0.f, 0.f);
            scs[j] = 0.f; idxs[j] = 0;
        }
    }

    unsigned keptm = 0;
    while (true) {
        unsigned long long best = ~0ULL;
        #pragma unroll
        for (int j = 0; j < 4; ++j) {
            if (alive & (1u << j)) {
                unsigned long long k =
                    ((unsigned long long)(~__float_as_uint(scs[j])) << 20) |
                    ((unsigned long long)(unsigned)idxs[j] << 10) |
                    (unsigned long long)(unsigned)(j * 32 + lane);
                if (k < best) best = k;
            }
        }
        #pragma unroll
        for (int o = 16; o; o >>= 1) {
            unsigned long long ob = __shfl_xor_sync(0xffffffffu, best, o);
            if (ob < best) best = ob;
        }
        if (best == ~0ULL) break;

        int e   = (int)(best & 1023ULL);
        int js  = e >> 5;
        int src = e & 31;
        float4 own = (js == 0) ? bxs[0] : (js == 1) ? bxs[1] : (js == 2) ? bxs[2] : bxs[3];
        float4 A;
        A.x = __shfl_sync(0xffffffffu, own.x, src);
        A.y = __shfl_sync(0xffffffffu, own.y, src);
        A.z = __shfl_sync(0xffffffffu, own.z, src);
        A.w = __shfl_sync(0xffffffffu, own.w, src);
        if (lane == src) {
            alive &= ~(1u << js);
            keptm |= (1u << js);
        }
        float areaA = (A.z - A.x) * (A.w - A.y);

        #pragma unroll
        for (int j = 0; j < 4; ++j) {
            if (alive & (1u << j)) {
                float4 Bx = bxs[j];
                float areaB = (Bx.z - Bx.x) * (Bx.w - Bx.y);
                float ltx = fmaxf(A.x, Bx.x), lty = fmaxf(A.y, Bx.y);
                float rbx = fminf(A.z, Bx.z), rby = fminf(A.w, Bx.w);
                float wx = fmaxf(rbx - ltx, 0.0f), wy = fmaxf(rby - lty, 0.0f);
                float inter = wx * wy;
                float iou = inter / (areaA + areaB - inter + 1e-9f);
                if (iou > NMS_THRESH) alive &= ~(1u << j);
            }
        }
    }

    // single aggregated atomic per warp, ballot-prefixed positions
    int pref[4];
    int kc = 0;
    #pragma unroll
    for (int j = 0; j < 4; ++j) {
        bool kept = (keptm >> j) & 1u;
        unsigned bal = __ballot_sync(0xffffffffu, kept);
        pref[j] = kc + __popc(bal & ((1u << lane) - 1u));
        kc += __popc(bal);
    }
    int basep = 0;
    if (lane == 0 && kc > 0) basep = atomicAdd(&g_M[b], kc);
    basep = __shfl_sync(0xffffffffu, basep, 0);
    #pragma unroll
    for (int j = 0; j < 4; ++j) {
        if ((keptm >> j) & 1u) {
            g_klist[b * NP + basep + pref[j]] =
                ((unsigned long long)(~__float_as_uint(scs[j])) << 10) |
                (unsigned long long)(unsigned)idxs[j];
        }
    }
}

// ---------------- Kernel C: top-100 rank counting, 4 entries per warp --------
// grid = NB * C_PARTS CTAs of 256 threads; no smem, no barriers.
__global__ __launch_bounds__(256) void topk_rank_kernel(float* __restrict__ out) {
    if (blockIdx.x == 0 && threadIdx.x < NB) g_maxc[threadIdx.x] = 0;

    const int img  = blockIdx.x / C_PARTS;
    const int part = blockIdx.x % C_PARTS;
    const int t    = threadIdx.x;
    const int warp = t >> 5;
    const int lane = t & 31;

    int M = g_M[img];
    if (M > NP) M = NP;

    float* boxes_out  = out;
    float* scores_out = out + NB * MAX_DET * 4;
    float* labels_out = out + NB * MAX_DET * 5;

    // default fill (part 0 only)
    const int filled = M < MAX_DET ? M : MAX_DET;
    if (part == 0 && t >= filled && t < MAX_DET) {
        int base = img * MAX_DET + t;
        boxes_out[base * 4 + 0] = 0.0f;
        boxes_out[base * 4 + 1] = 0.0f;
        boxes_out[base * 4 + 2] = 0.0f;
        boxes_out[base * 4 + 3] = 0.0f;
        scores_out[base] = 0.0f;
        labels_out[base] = -1.0f;
    }

    const unsigned long long* keys = g_klist + (size_t)img * NP;
    const int e0 = part * 32 + warp * 4;
    if (e0 >= M) return;

    // broadcast-load up to 4 entry keys (valid keys are always < ~0ULL)
    unsigned long long k0 = (e0 + 0 < M) ? __ldg(keys + e0 + 0) : ~0ULL;
    unsigned long long k1 = (e0 + 1 < M) ? __ldg(keys + e0 + 1) : ~0ULL;
    unsigned long long k2 = (e0 + 2 < M) ? __ldg(keys + e0 + 2) : ~0ULL;
    unsigned long long k3 = (e0 + 3 < M) ? __ldg(keys + e0 + 3) : ~0ULL;

    int r0 = 0, r1 = 0, r2 = 0, r3 = 0;
    #pragma unroll 4
    for (int j = lane; j < M; j += 32) {
        unsigned long long kj = __ldg(keys + j);
        r0 += (kj < k0);
        r1 += (kj < k1);
        r2 += (kj < k2);
        r3 += (kj < k3);
    }
    #pragma unroll
    for (int o = 16; o; o >>= 1) {
        r0 += __shfl_xor_sync(0xffffffffu, r0, o);
        r1 += __shfl_xor_sync(0xffffffffu, r1, o);
        r2 += __shfl_xor_sync(0xffffffffu, r2, o);
        r3 += __shfl_xor_sync(0xffffffffu, r3, o);
    }

    if (lane == 0) {
        unsigned long long ks[4] = {k0, k1, k2, k3};
        int rs[4] = {r0, r1, r2, r3};
        #pragma unroll
        for (int i = 0; i < 4; ++i) {
            if (e0 + i < M && rs[i] < MAX_DET) {
                int idx = (int)(ks[i] & 1023ULL);
                int g = img * NP + idx;
                float4 v = g_boxes[g];
                int base = img * MAX_DET + rs[i];
                boxes_out[base * 4 + 0] = v.x;
                boxes_out[base * 4 + 1] = v.y;
                boxes_out[base * 4 + 2] = v.z;
                boxes_out[base * 4 + 3] = v.w;
                scores_out[base] = g_scores[g];
                labels_out[base] = (float)g_labels[g];
            }
        }
    }
}

// ---------------- launch ----------------
extern "C" void kernel_launch(void* const* d_in, const int* in_sizes, int n_in,
                              void* d_out, int out_size) {
    const float* class_logits  = (const float*)d_in[0];
    const float* bbox_deltas   = (const float*)d_in[1];
    const float* roi_proposals = (const float*)d_in[2];
    const int*   image_sizes   = (const int*)d_in[3];
    float* out = (float*)d_out;

    // A: one warp per 2 proposals -> 8192 warps -> 1024 CTAs of 256 threads
    int warpsA  = (NB * NP) / 2;
    int blocksA = (warpsA * 32) / 256;
    score_decode_kernel<<<blocksA, 256>>>(class_logits, bbox_deltas,
                                          roi_proposals, image_sizes);

    int nmsWarps = NB * 90;
    int nmsBlocks = (nmsWarps * 32 + 255) / 256;
    nms_class_kernel<<<nmsBlocks, 256>>>();

    topk_rank_kernel<<<NB * C_PARTS, 256>>>(out);
}

// round 15
// speedup vs baseline: 1.1624x; 1.1156x over previous
#include <cuda_runtime.h>
#include <float.h>
#include <math.h>

#define NB 16
#define NP 1024
#define NC 91
#define MAX_DET 100
#define SCORE_THRESH 0.05f
#define NMS_THRESH 0.5f
#define BBOX_CLIP 4.135166556742356f  /* log(1000/16) */
#define BK 128                        /* bucket capacity per (image,class) */
#define LOG2E 1.4426950408889634f
#define LN2   0.6931471805599453f

#define C_PARTS 32                    /* 32 entries per part-CTA */

// ---------------- scratch (no allocations allowed) ----------------
__device__ float  g_scores[NB * NP];
__device__ int    g_labels[NB * NP];           // 0 if invalid, else 1..90
__device__ float4 g_boxes[NB * NP];

__device__ int    g_bcnt[NB * 91];             // bucket counts   (reset by B owner-warps)
__device__ float4 g_bbox[NB * 91 * BK];        // bucket boxes (raw clipped)
__device__ float  g_bsc [NB * 91 * BK];        // bucket scores
__device__ int    g_bidx[NB * 91 * BK];        // bucket original idx (0..1023)
__device__ int    g_maxc[NB];                  // per-image max coord (reset by C)
__device__ int    g_M[NB];                     // kept count per image (reset by A)
__device__ unsigned long long g_klist[NB * NP];// kept keys per image (contiguous)

// monotone injective float <-> ordinal-uint maps
__device__ __forceinline__ unsigned f2ord(float x) {
    unsigned u = __float_as_uint(x);
    return (u & 0x80000000u) ? ~u : (u | 0x80000000u);
}
__device__ __forceinline__ float ord2f(unsigned u) {
    return __uint_as_float((u & 0x80000000u) ? (u ^ 0x80000000u) : ~u);
}

// e^x for x <= BBOX_CLIP, pure FMA/ALU pipes (no MUFU). Max rel err ~5e-9 + rounding.
__device__ __forceinline__ float exp_poly(float x) {
    float y = x * LOG2E;
    y = fmaxf(y, -126.0f);          // underflow -> 2^-126 * p ~ 0 (harmless)
    float r = rintf(y);             // n = round(y); f = y - n in [-0.5, 0.5]
    float f = y - r;
    float t = f * LN2;              // |t| <= 0.3466
    float p = 1.9841270114e-4f;     // 1/7!
    p = fmaf(p, t, 1.3888888961e-3f);   // 1/6!
    p = fmaf(p, t, 8.3333337680e-3f);   // 1/5!
    p = fmaf(p, t, 4.1666667908e-2f);   // 1/4!
    p = fmaf(p, t, 1.6666667163e-1f);   // 1/3!
    p = fmaf(p, t, 5.0000000000e-1f);   // 1/2!
    p = fmaf(p, t, 1.0f);
    p = fmaf(p, t, 1.0f);
    int n = (int)r;                 // n in [-126, 6]
    return __uint_as_float((unsigned)(n + 127) << 23) * p;   // 2^n * e^t
}

// ---------------- Kernel A: softmax-max/argmax + decode + clip + bucket ------
// One warp per FOUR proposals (4k..4k+3 — always same image). CTA = 64 props
// of ONE image. 4096 warps total.
__global__ __launch_bounds__(256) void score_decode_kernel(
        const float* __restrict__ logits,
        const float* __restrict__ deltas,
        const float* __restrict__ props,
        const int*   __restrict__ imsz) {
    __shared__ unsigned s_mc[8];

    if (blockIdx.x == 0 && threadIdx.x < NB) g_M[threadIdx.x] = 0;

    const int warpid = (blockIdx.x * blockDim.x + threadIdx.x) >> 5;
    const int warp   = (threadIdx.x) >> 5;
    const int lane   = threadIdx.x & 31;
    const int pa     = warpid * 4;                 // first proposal of the quad
    const int b      = pa >> 10;                   // all 4 share the image

    // tail-lane loads (lanes 0..3 own proposals pa..pa+3)
    float4 pr;
    int ih = 0, iw = 0;
    const int myP = pa + lane;
    if (lane < 4) {
        pr = *reinterpret_cast<const float4*>(props + (size_t)myP * 4);
        ih = imsz[b * 2 + 0];
        iw = imsz[b * 2 + 1];
    }

    // 12 logit loads up-front (MLP 12)
    const float* r0 = logits + (size_t)pa * NC;
    const float* r1 = r0 + NC;
    const float* r2 = r1 + NC;
    const float* r3 = r2 + NC;
    const bool has2 = (lane < NC - 64);            // lane < 27
    float a0 = r0[lane], a1 = r0[lane + 32];
    float b0 = r1[lane], b1 = r1[lane + 32];
    float c0 = r2[lane], c1 = r2[lane + 32];
    float d0 = r3[lane], d1 = r3[lane + 32];
    float a2 = has2 ? r0[lane + 64] : -FLT_MAX;
    float b2 = has2 ? r1[lane + 64] : -FLT_MAX;
    float c2 = has2 ? r2[lane + 64] : -FLT_MAX;
    float d2 = has2 ? r3[lane + 64] : -FLT_MAX;

    // lane-local argmax (ascending index + strict > = first-index tiebreak)
    unsigned ua = f2ord(a0); int ia = lane;
    { unsigned u = f2ord(a1); if (u > ua) { ua = u; ia = lane + 32; }
      u = f2ord(a2);          if (u > ua) { ua = u; ia = lane + 64; } }
    unsigned ub = f2ord(b0); int ib = lane;
    { unsigned u = f2ord(b1); if (u > ub) { ub = u; ib = lane + 32; }
      u = f2ord(b2);          if (u > ub) { ub = u; ib = lane + 64; } }
    unsigned uc = f2ord(c0); int ic = lane;
    { unsigned u = f2ord(c1); if (u > uc) { uc = u; ic = lane + 32; }
      u = f2ord(c2);          if (u > uc) { uc = u; ic = lane + 64; } }
    unsigned ud = f2ord(d0); int id = lane;
    { unsigned u = f2ord(d1); if (u > ud) { ud = u; id = lane + 32; }
      u = f2ord(d2);          if (u > ud) { ud = u; id = lane + 64; } }

    // warp argmax via REDUX (max value, then min index among achievers)
    unsigned uam = __reduce_max_sync(0xffffffffu, ua);
    unsigned ubm = __reduce_max_sync(0xffffffffu, ub);
    unsigned ucm = __reduce_max_sync(0xffffffffu, uc);
    unsigned udm = __reduce_max_sync(0xffffffffu, ud);
    int lA = (int)__reduce_min_sync(0xffffffffu, (ua == uam) ? (unsigned)ia : 0x7fffffffu);
    int lB = (int)__reduce_min_sync(0xffffffffu, (ub == ubm) ? (unsigned)ib : 0x7fffffffu);
    int lC = (int)__reduce_min_sync(0xffffffffu, (uc == ucm) ? (unsigned)ic : 0x7fffffffu);
    int lD = (int)__reduce_min_sync(0xffffffffu, (ud == udm) ? (unsigned)id : 0x7fffffffu);
    float mA = ord2f(uam), mB = ord2f(ubm), mC = ord2f(ucm), mD = ord2f(udm);

    // softmax denominators: FMA-pipe exp, butterfly reduce (all 4 together)
    float sa = exp_poly(a0 - mA) + exp_poly(a1 - mA) + (has2 ? exp_poly(a2 - mA) : 0.0f);
    float sb = exp_poly(b0 - mB) + exp_poly(b1 - mB) + (has2 ? exp_poly(b2 - mB) : 0.0f);
    float sc = exp_poly(c0 - mC) + exp_poly(c1 - mC) + (has2 ? exp_poly(c2 - mC) : 0.0f);
    float sd = exp_poly(d0 - mD) + exp_poly(d1 - mD) + (has2 ? exp_poly(d2 - mD) : 0.0f);
    #pragma unroll
    for (int o = 16; o; o >>= 1) {
        sa += __shfl_xor_sync(0xffffffffu, sa, o);
        sb += __shfl_xor_sync(0xffffffffu, sb, o);
        sc += __shfl_xor_sync(0xffffffffu, sc, o);
        sd += __shfl_xor_sync(0xffffffffu, sd, o);
    }

    // decode: lanes 0..3 handle proposals pa..pa+3 concurrently
    float mc = 0.0f;   // per-thread contribution to image max-coord (0 if invalid/idle)
    if (lane < 4) {
        float ssum  = (lane == 0) ? sa : (lane == 1) ? sb : (lane == 2) ? sc : sd;
        int   label = (lane == 0) ? lA : (lane == 1) ? lB : (lane == 2) ? lC : lD;
        float score = 1.0f / ssum;
        int   valid = (label > 0) && (score > SCORE_THRESH);

        float x1 = pr.x, y1 = pr.y, x2 = pr.z, y2 = pr.w;
        float w = x2 - x1, h = y2 - y1;
        float cx = x1 + 0.5f * w, cy = y1 + 0.5f * h;

        const float* dd = deltas + (size_t)myP * (NC * 4) + 4 * label;
        float dx = dd[0], dy = dd[1];
        float dw = fminf(dd[2], BBOX_CLIP), dh = fminf(dd[3], BBOX_CLIP);
        float pcx = dx * w + cx, pcy = dy * h + cy;
        float pw = exp_poly(dw) * w, ph = exp_poly(dh) * h;
        float bx1 = pcx - 0.5f * pw, by1 = pcy - 0.5f * ph;
        float bx2 = pcx + 0.5f * pw, by2 = pcy + 0.5f * ph;

        float hb = (float)ih;
        float wb = (float)iw;
        bx1 = fminf(fmaxf(bx1, 0.0f), wb);
        by1 = fminf(fmaxf(by1, 0.0f), hb);
        bx2 = fminf(fmaxf(bx2, 0.0f), wb);
        by2 = fminf(fmaxf(by2, 0.0f), hb);

        g_boxes[myP]  = make_float4(bx1, by1, bx2, by2);
        g_scores[myP] = score;
        g_labels[myP] = valid ? label : 0;

        if (valid) {
            mc = fmaxf(fmaxf(bx1, by1), fmaxf(bx2, by2));   // >= 0
            int bc = b * 91 + label;
            int p2 = atomicAdd(&g_bcnt[bc], 1);
            if (p2 < BK) {
                int slot = bc * BK + p2;
                g_bbox[slot] = make_float4(bx1, by1, bx2, by2);
                g_bsc[slot]  = score;
                g_bidx[slot] = myP - b * NP;
            }
        }
    }

    // CTA-aggregated max-coord: all 64 proposals of this CTA share image b.
    // coords >= 0 -> raw float bits are monotone; exact, order-independent.
    unsigned mu = __reduce_max_sync(0xffffffffu, __float_as_uint(mc));
    if (lane == 0) s_mc[warp] = mu;
    __syncthreads();
    if (threadIdx.x == 0) {
        unsigned m = s_mc[0];
        #pragma unroll
        for (int i = 1; i < 8; ++i) m = m > s_mc[i] ? m : s_mc[i];
        atomicMax(&g_maxc[b], (int)m);
    }
}

// ---------------- Kernel B: NMS, one warp per (image, class), registers only ----
// Kept keys appended to the image's contiguous list with ONE atomic per warp.
// Each warp resets its own g_bcnt[bc] after reading it (sole owner).
__global__ __launch_bounds__(256) void nms_class_kernel() {
    int gwarp = (blockIdx.x * blockDim.x + threadIdx.x) >> 5;
    int lane  = threadIdx.x & 31;
    if (gwarp >= NB * 90) return;
    int b = gwarp / 90;
    int c = 1 + gwarp % 90;
    int bc = b * 91 + c;

    int n = g_bcnt[bc];
    __syncwarp();
    if (lane == 0 && n != 0) g_bcnt[bc] = 0;   // reset for next replay
    if (n > BK) n = BK;
    if (n == 0) return;

    float K   = __int_as_float(g_maxc[b]) + 1.0f;
    float off = (float)c * K;    // label * (max_coord + 1), reference FP order

    float4 bxs[4]; float scs[4]; int idxs[4];
    unsigned alive = 0;
    #pragma unroll
    for (int j = 0; j < 4; ++j) {
        int e = j * 32 + lane;
        if (e < n) {
            float4 v = g_bbox[bc * BK + e];
            bxs[j] = make_float4(v.x + off, v.y + off, v.z + off, v.w + off);
            scs[j] = g_bsc[bc * BK + e];
            idxs[j] = g_bidx[bc * BK + e];
            alive |= (1u << j);
        } else {
            bxs[j] = make_float4(0.f, 0.f, 0.f, 0.f);
            scs[j] = 0.f; idxs[j] = 0;
        }
    }

    unsigned keptm = 0;
    while (true) {
        unsigned long long best = ~0ULL;
        #pragma unroll
        for (int j = 0; j < 4; ++j) {
            if (alive & (1u << j)) {
                unsigned long long k =
                    ((unsigned long long)(~__float_as_uint(scs[j])) << 20) |
                    ((unsigned long long)(unsigned)idxs[j] << 10) |
                    (unsigned long long)(unsigned)(j * 32 + lane);
                if (k < best) best = k;
            }
        }
        #pragma unroll
        for (int o = 16; o; o >>= 1) {
            unsigned long long ob = __shfl_xor_sync(0xffffffffu, best, o);
            if (ob < best) best = ob;
        }
        if (best == ~0ULL) break;

        int e   = (int)(best & 1023ULL);
        int js  = e >> 5;
        int src = e & 31;
        float4 own = (js == 0) ? bxs[0] : (js == 1) ? bxs[1] : (js == 2) ? bxs[2] : bxs[3];
        float4 A;
        A.x = __shfl_sync(0xffffffffu, own.x, src);
        A.y = __shfl_sync(0xffffffffu, own.y, src);
        A.z = __shfl_sync(0xffffffffu, own.z, src);
        A.w = __shfl_sync(0xffffffffu, own.w, src);
        if (lane == src) {
            alive &= ~(1u << js);
            keptm |= (1u << js);
        }
        float areaA = (A.z - A.x) * (A.w - A.y);

        #pragma unroll
        for (int j = 0; j < 4; ++j) {
            if (alive & (1u << j)) {
                float4 Bx = bxs[j];
                float areaB = (Bx.z - Bx.x) * (Bx.w - Bx.y);
                float ltx = fmaxf(A.x, Bx.x), lty = fmaxf(A.y, Bx.y);
                float rbx = fminf(A.z, Bx.z), rby = fminf(A.w, Bx.w);
                float wx = fmaxf(rbx - ltx, 0.0f), wy = fmaxf(rby - lty, 0.0f);
                float inter = wx * wy;
                float iou = inter / (areaA + areaB - inter + 1e-9f);
                if (iou > NMS_THRESH) alive &= ~(1u << j);
            }
        }
    }

    // single aggregated atomic per warp, ballot-prefixed positions
    int pref[4];
    int kc = 0;
    #pragma unroll
    for (int j = 0; j < 4; ++j) {
        bool kept = (keptm >> j) & 1u;
        unsigned bal = __ballot_sync(0xffffffffu, kept);
        pref[j] = kc + __popc(bal & ((1u << lane) - 1u));
        kc += __popc(bal);
    }
    int basep = 0;
    if (lane == 0 && kc > 0) basep = atomicAdd(&g_M[b], kc);
    basep = __shfl_sync(0xffffffffu, basep, 0);
    #pragma unroll
    for (int j = 0; j < 4; ++j) {
        if ((keptm >> j) & 1u) {
            g_klist[b * NP + basep + pref[j]] =
                ((unsigned long long)(~__float_as_uint(scs[j])) << 10) |
                (unsigned long long)(unsigned)idxs[j];
        }
    }
}

// ---------------- Kernel C: top-100 rank counting, 4 entries per warp --------
// grid = NB * C_PARTS CTAs of 256 threads; no smem, no barriers.
__global__ __launch_bounds__(256) void topk_rank_kernel(float* __restrict__ out) {
    if (blockIdx.x == 0 && threadIdx.x < NB) g_maxc[threadIdx.x] = 0;

    const int img  = blockIdx.x / C_PARTS;
    const int part = blockIdx.x % C_PARTS;
    const int t    = threadIdx.x;
    const int warp = t >> 5;
    const int lane = t & 31;

    int M = g_M[img];
    if (M > NP) M = NP;

    float* boxes_out  = out;
    float* scores_out = out + NB * MAX_DET * 4;
    float* labels_out = out + NB * MAX_DET * 5;

    // default fill (part 0 only)
    const int filled = M < MAX_DET ? M : MAX_DET;
    if (part == 0 && t >= filled && t < MAX_DET) {
        int base = img * MAX_DET + t;
        boxes_out[base * 4 + 0] = 0.0f;
        boxes_out[base * 4 + 1] = 0.0f;
        boxes_out[base * 4 + 2] = 0.0f;
        boxes_out[base * 4 + 3] = 0.0f;
        scores_out[base] = 0.0f;
        labels_out[base] = -1.0f;
    }

    const unsigned long long* keys = g_klist + (size_t)img * NP;
    const int e0 = part * 32 + warp * 4;
    if (e0 >= M) return;

    // broadcast-load up to 4 entry keys (valid keys are always < ~0ULL)
    unsigned long long k0 = (e0 + 0 < M) ? __ldg(keys + e0 + 0) : ~0ULL;
    unsigned long long k1 = (e0 + 1 < M) ? __ldg(keys + e0 + 1) : ~0ULL;
    unsigned long long k2 = (e0 + 2 < M) ? __ldg(keys + e0 + 2) : ~0ULL;
    unsigned long long k3 = (e0 + 3 < M) ? __ldg(keys + e0 + 3) : ~0ULL;

    int r0 = 0, r1 = 0, r2 = 0, r3 = 0;
    #pragma unroll 4
    for (int j = lane; j < M; j += 32) {
        unsigned long long kj = __ldg(keys + j);
        r0 += (kj < k0);
        r1 += (kj < k1);
        r2 += (kj < k2);
        r3 += (kj < k3);
    }
    #pragma unroll
    for (int o = 16; o; o >>= 1) {
        r0 += __shfl_xor_sync(0xffffffffu, r0, o);
        r1 += __shfl_xor_sync(0xffffffffu, r1, o);
        r2 += __shfl_xor_sync(0xffffffffu, r2, o);
        r3 += __shfl_xor_sync(0xffffffffu, r3, o);
    }

    if (lane == 0) {
        unsigned long long ks[4] = {k0, k1, k2, k3};
        int rs[4] = {r0, r1, r2, r3};
        #pragma unroll
        for (int i = 0; i < 4; ++i) {
            if (e0 + i < M && rs[i] < MAX_DET) {
                int idx = (int)(ks[i] & 1023ULL);
                int g = img * NP + idx;
                float4 v = g_boxes[g];
                int base = img * MAX_DET + rs[i];
                boxes_out[base * 4 + 0] = v.x;
                boxes_out[base * 4 + 1] = v.y;
                boxes_out[base * 4 + 2] = v.z;
                boxes_out[base * 4 + 3] = v.w;
                scores_out[base] = g_scores[g];
                labels_out[base] = (float)g_labels[g];
            }
        }
    }
}

// ---------------- launch ----------------
extern "C" void kernel_launch(void* const* d_in, const int* in_sizes, int n_in,
                              void* d_out, int out_size) {
    const float* class_logits  = (const float*)d_in[0];
    const float* bbox_deltas   = (const float*)d_in[1];
    const float* roi_proposals = (const float*)d_in[2];
    const int*   image_sizes   = (const int*)d_in[3];
    float* out = (float*)d_out;

    // A: one warp per 4 proposals -> 4096 warps -> 512 CTAs of 256 threads
    int warpsA  = (NB * NP) / 4;
    int blocksA = (warpsA * 32) / 256;
    score_decode_kernel<<<blocksA, 256>>>(class_logits, bbox_deltas,
                                          roi_proposals, image_sizes);

    int nmsWarps = NB * 90;
    int nmsBlocks = (nmsWarps * 32 + 255) / 256;
    nms_class_kernel<<<nmsBlocks, 256>>>();

    topk_rank_kernel<<<NB * C_PARTS, 256>>>(out);
}

// round 16
// speedup vs baseline: 1.2368x; 1.0640x over previous
#include <cuda_runtime.h>
#include <float.h>
#include <math.h>

#define NB 16
#define NP 1024
#define NC 91
#define MAX_DET 100
#define SCORE_THRESH 0.05f
#define NMS_THRESH 0.5f
#define BBOX_CLIP 4.135166556742356f  /* log(1000/16) */
#define BK 128                        /* bucket capacity per (image,class) */
#define LOG2E 1.4426950408889634f
#define LN2   0.6931471805599453f

#define PW 8                          /* proposals per warp in kernel A */
#define C_PARTS 32                    /* 32 entries per part-CTA */

// ---------------- scratch (no allocations allowed) ----------------
__device__ float  g_scores[NB * NP];
__device__ int    g_labels[NB * NP];           // 0 if invalid, else 1..90
__device__ float4 g_boxes[NB * NP];

__device__ int    g_bcnt[NB * 91];             // bucket counts   (reset by B owner-warps)
__device__ float4 g_bbox[NB * 91 * BK];        // bucket boxes (raw clipped)
__device__ float  g_bsc [NB * 91 * BK];        // bucket scores
__device__ int    g_bidx[NB * 91 * BK];        // bucket original idx (0..1023)
__device__ int    g_maxc[NB];                  // per-image max coord (reset by C)
__device__ int    g_M[NB];                     // kept count per image (reset by A)
__device__ unsigned long long g_klist[NB * NP];// kept keys per image (contiguous)

// monotone injective float <-> ordinal-uint maps
__device__ __forceinline__ unsigned f2ord(float x) {
    unsigned u = __float_as_uint(x);
    return (u & 0x80000000u) ? ~u : (u | 0x80000000u);
}
__device__ __forceinline__ float ord2f(unsigned u) {
    return __uint_as_float((u & 0x80000000u) ? (u ^ 0x80000000u) : ~u);
}

// e^x for x <= BBOX_CLIP, pure FMA/ALU pipes (no MUFU). Max rel err ~5e-9 + rounding.
__device__ __forceinline__ float exp_poly(float x) {
    float y = x * LOG2E;
    y = fmaxf(y, -126.0f);          // underflow -> 2^-126 * p ~ 0 (harmless)
    float r = rintf(y);             // n = round(y); f = y - n in [-0.5, 0.5]
    float f = y - r;
    float t = f * LN2;              // |t| <= 0.3466
    float p = 1.9841270114e-4f;     // 1/7!
    p = fmaf(p, t, 1.3888888961e-3f);   // 1/6!
    p = fmaf(p, t, 8.3333337680e-3f);   // 1/5!
    p = fmaf(p, t, 4.1666667908e-2f);   // 1/4!
    p = fmaf(p, t, 1.6666667163e-1f);   // 1/3!
    p = fmaf(p, t, 5.0000000000e-1f);   // 1/2!
    p = fmaf(p, t, 1.0f);
    p = fmaf(p, t, 1.0f);
    int n = (int)r;                 // n in [-126, 6]
    return __uint_as_float((unsigned)(n + 127) << 23) * p;   // 2^n * e^t
}

// ---------------- Kernel A: softmax-max/argmax + decode + clip + bucket ------
// One warp per PW=8 proposals (8k..8k+7 — always same image). CTA = 64 props
// of ONE image. 2048 warps total.
__global__ __launch_bounds__(256) void score_decode_kernel(
        const float* __restrict__ logits,
        const float* __restrict__ deltas,
        const float* __restrict__ props,
        const int*   __restrict__ imsz) {
    __shared__ unsigned s_mc[8];

    if (blockIdx.x == 0 && threadIdx.x < NB) g_M[threadIdx.x] = 0;

    const int warpid = (blockIdx.x * blockDim.x + threadIdx.x) >> 5;
    const int warp   = threadIdx.x >> 5;
    const int lane   = threadIdx.x & 31;
    const int pa     = warpid * PW;                // first proposal of the group
    const int b      = pa >> 10;                   // all PW share the image

    // tail-lane loads (lanes 0..PW-1 own proposals pa..pa+PW-1)
    float4 pr;
    int ih = 0, iw = 0;
    const int myP = pa + lane;
    if (lane < PW) {
        pr = *reinterpret_cast<const float4*>(props + (size_t)myP * 4);
        ih = imsz[b * 2 + 0];
        iw = imsz[b * 2 + 1];
    }

    // 3*PW logit loads up-front (MLP 24)
    const bool has2 = (lane < NC - 64);            // lane < 27
    float L0[PW], L1[PW], L2[PW];
    #pragma unroll
    for (int i = 0; i < PW; ++i) {
        const float* r = logits + (size_t)(pa + i) * NC;
        L0[i] = r[lane];
        L1[i] = r[lane + 32];
        L2[i] = has2 ? r[lane + 64] : -FLT_MAX;
    }

    // lane-local argmax (ascending index + strict > = first-index tiebreak)
    unsigned um[PW]; int im[PW];
    #pragma unroll
    for (int i = 0; i < PW; ++i) {
        unsigned u0 = f2ord(L0[i]); int ii = lane;
        unsigned u = f2ord(L1[i]); if (u > u0) { u0 = u; ii = lane + 32; }
        u = f2ord(L2[i]);          if (u > u0) { u0 = u; ii = lane + 64; }
        um[i] = u0; im[i] = ii;
    }

    // warp argmax via REDUX (max value, then min index among achievers)
    unsigned uM[PW]; int lab[PW]; float mv[PW];
    #pragma unroll
    for (int i = 0; i < PW; ++i) uM[i] = __reduce_max_sync(0xffffffffu, um[i]);
    #pragma unroll
    for (int i = 0; i < PW; ++i)
        lab[i] = (int)__reduce_min_sync(0xffffffffu,
                    (um[i] == uM[i]) ? (unsigned)im[i] : 0x7fffffffu);
    #pragma unroll
    for (int i = 0; i < PW; ++i) mv[i] = ord2f(uM[i]);

    // softmax denominators: FMA-pipe exp, butterfly reduce (all PW together)
    float s[PW];
    #pragma unroll
    for (int i = 0; i < PW; ++i)
        s[i] = exp_poly(L0[i] - mv[i]) + exp_poly(L1[i] - mv[i]) +
               (has2 ? exp_poly(L2[i] - mv[i]) : 0.0f);
    #pragma unroll
    for (int o = 16; o; o >>= 1) {
        #pragma unroll
        for (int i = 0; i < PW; ++i)
            s[i] += __shfl_xor_sync(0xffffffffu, s[i], o);
    }

    // decode: lanes 0..PW-1 handle proposals pa..pa+PW-1 concurrently
    float mc = 0.0f;   // per-thread contribution to image max-coord
    if (lane < PW) {
        float ssum = s[0]; int label = lab[0];
        #pragma unroll
        for (int i = 1; i < PW; ++i)
            if (lane == i) { ssum = s[i]; label = lab[i]; }
        float score = 1.0f / ssum;
        int   valid = (label > 0) && (score > SCORE_THRESH);

        float x1 = pr.x, y1 = pr.y, x2 = pr.z, y2 = pr.w;
        float w = x2 - x1, h = y2 - y1;
        float cx = x1 + 0.5f * w, cy = y1 + 0.5f * h;

        const float* dd = deltas + (size_t)myP * (NC * 4) + 4 * label;
        float dx = dd[0], dy = dd[1];
        float dw = fminf(dd[2], BBOX_CLIP), dh = fminf(dd[3], BBOX_CLIP);
        float pcx = dx * w + cx, pcy = dy * h + cy;
        float pw = exp_poly(dw) * w, ph = exp_poly(dh) * h;
        float bx1 = pcx - 0.5f * pw, by1 = pcy - 0.5f * ph;
        float bx2 = pcx + 0.5f * pw, by2 = pcy + 0.5f * ph;

        float hb = (float)ih;
        float wb = (float)iw;
        bx1 = fminf(fmaxf(bx1, 0.0f), wb);
        by1 = fminf(fmaxf(by1, 0.0f), hb);
        bx2 = fminf(fmaxf(bx2, 0.0f), wb);
        by2 = fminf(fmaxf(by2, 0.0f), hb);

        g_boxes[myP]  = make_float4(bx1, by1, bx2, by2);
        g_scores[myP] = score;
        g_labels[myP] = valid ? label : 0;

        if (valid) {
            mc = fmaxf(fmaxf(bx1, by1), fmaxf(bx2, by2));   // >= 0
            int bc = b * 91 + label;
            int p2 = atomicAdd(&g_bcnt[bc], 1);
            if (p2 < BK) {
                int slot = bc * BK + p2;
                g_bbox[slot] = make_float4(bx1, by1, bx2, by2);
                g_bsc[slot]  = score;
                g_bidx[slot] = myP - b * NP;
            }
        }
    }

    // CTA-aggregated max-coord: all 64 proposals of this CTA share image b.
    // coords >= 0 -> raw float bits are monotone; exact, order-independent.
    unsigned mu = __reduce_max_sync(0xffffffffu, __float_as_uint(mc));
    if (lane == 0) s_mc[warp] = mu;
    __syncthreads();
    if (threadIdx.x == 0) {
        unsigned m = s_mc[0];
        #pragma unroll
        for (int i = 1; i < 8; ++i) m = m > s_mc[i] ? m : s_mc[i];
        atomicMax(&g_maxc[b], (int)m);
    }
}

// ---------------- Kernel B: NMS, one warp per (image, class), registers only ----
// Kept keys appended to the image's contiguous list with ONE atomic per warp.
// Each warp resets its own g_bcnt[bc] after reading it (sole owner).
__global__ __launch_bounds__(256) void nms_class_kernel() {
    int gwarp = (blockIdx.x * blockDim.x + threadIdx.x) >> 5;
    int lane  = threadIdx.x & 31;
    if (gwarp >= NB * 90) return;
    int b = gwarp / 90;
    int c = 1 + gwarp % 90;
    int bc = b * 91 + c;

    int n = g_bcnt[bc];
    __syncwarp();
    if (lane == 0 && n != 0) g_bcnt[bc] = 0;   // reset for next replay
    if (n > BK) n = BK;
    if (n == 0) return;

    float K   = __int_as_float(g_maxc[b]) + 1.0f;
    float off = (float)c * K;    // label * (max_coord + 1), reference FP order

    float4 bxs[4]; float scs[4]; int idxs[4];
    unsigned alive = 0;
    #pragma unroll
    for (int j = 0; j < 4; ++j) {
        int e = j * 32 + lane;
        if (e < n) {
            float4 v = g_bbox[bc * BK + e];
            bxs[j] = make_float4(v.x + off, v.y + off, v.z + off, v.w + off);
            scs[j] = g_bsc[bc * BK + e];
            idxs[j] = g_bidx[bc * BK + e];
            alive |= (1u << j);
        } else {
            bxs[j] = make_float4(0.f, 0.f, 0.f, 0.f);
            scs[j] = 0.f; idxs[j] = 0;
        }
    }

    unsigned keptm = 0;
    while (true) {
        unsigned long long best = ~0ULL;
        #pragma unroll
        for (int j = 0; j < 4; ++j) {
            if (alive & (1u << j)) {
                unsigned long long k =
                    ((unsigned long long)(~__float_as_uint(scs[j])) << 20) |
                    ((unsigned long long)(unsigned)idxs[j] << 10) |
                    (unsigned long long)(unsigned)(j * 32 + lane);
                if (k < best) best = k;
            }
        }
        #pragma unroll
        for (int o = 16; o; o >>= 1) {
            unsigned long long ob = __shfl_xor_sync(0xffffffffu, best, o);
            if (ob < best) best = ob;
        }
        if (best == ~0ULL) break;

        int e   = (int)(best & 1023ULL);
        int js  = e >> 5;
        int src = e & 31;
        float4 own = (js == 0) ? bxs[0] : (js == 1) ? bxs[1] : (js == 2) ? bxs[2] : bxs[3];
        float4 A;
        A.x = __shfl_sync(0xffffffffu, own.x, src);
        A.y = __shfl_sync(0xffffffffu, own.y, src);
        A.z = __shfl_sync(0xffffffffu, own.z, src);
        A.w = __shfl_sync(0xffffffffu, own.w, src);
        if (lane == src) {
            alive &= ~(1u << js);
            keptm |= (1u << js);
        }
        float areaA = (A.z - A.x) * (A.w - A.y);

        #pragma unroll
        for (int j = 0; j < 4; ++j) {
            if (alive & (1u << j)) {
                float4 Bx = bxs[j];
                float areaB = (Bx.z - Bx.x) * (Bx.w - Bx.y);
                float ltx = fmaxf(A.x, Bx.x), lty = fmaxf(A.y, Bx.y);
                float rbx = fminf(A.z, Bx.z), rby = fminf(A.w, Bx.w);
                float wx = fmaxf(rbx - ltx, 0.0f), wy = fmaxf(rby - lty, 0.0f);
                float inter = wx * wy;
                float iou = inter / (areaA + areaB - inter + 1e-9f);
                if (iou > NMS_THRESH) alive &= ~(1u << j);
            }
        }
    }

    // single aggregated atomic per warp, ballot-prefixed positions
    int pref[4];
    int kc = 0;
    #pragma unroll
    for (int j = 0; j < 4; ++j) {
        bool kept = (keptm >> j) & 1u;
        unsigned bal = __ballot_sync(0xffffffffu, kept);
        pref[j] = kc + __popc(bal & ((1u << lane) - 1u));
        kc += __popc(bal);
    }
    int basep = 0;
    if (lane == 0 && kc > 0) basep = atomicAdd(&g_M[b], kc);
    basep = __shfl_sync(0xffffffffu, basep, 0);
    #pragma unroll
    for (int j = 0; j < 4; ++j) {
        if ((keptm >> j) & 1u) {
            g_klist[b * NP + basep + pref[j]] =
                ((unsigned long long)(~__float_as_uint(scs[j])) << 10) |
                (unsigned long long)(unsigned)idxs[j];
        }
    }
}

// ---------------- Kernel C: top-100 rank counting, 4 entries per warp --------
// grid = NB * C_PARTS CTAs of 256 threads; no smem, no barriers.
__global__ __launch_bounds__(256) void topk_rank_kernel(float* __restrict__ out) {
    if (blockIdx.x == 0 && threadIdx.x < NB) g_maxc[threadIdx.x] = 0;

    const int img  = blockIdx.x / C_PARTS;
    const int part = blockIdx.x % C_PARTS;
    const int t    = threadIdx.x;
    const int warp = t >> 5;
    const int lane = t & 31;

    int M = g_M[img];
    if (M > NP) M = NP;

    float* boxes_out  = out;
    float* scores_out = out + NB * MAX_DET * 4;
    float* labels_out = out + NB * MAX_DET * 5;

    // default fill (part 0 only)
    const int filled = M < MAX_DET ? M : MAX_DET;
    if (part == 0 && t >= filled && t < MAX_DET) {
        int base = img * MAX_DET + t;
        boxes_out[base * 4 + 0] = 0.0f;
        boxes_out[base * 4 + 1] = 0.0f;
        boxes_out[base * 4 + 2] = 0.0f;
        boxes_out[base * 4 + 3] = 0.0f;
        scores_out[base] = 0.0f;
        labels_out[base] = -1.0f;
    }

    const unsigned long long* keys = g_klist + (size_t)img * NP;
    const int e0 = part * 32 + warp * 4;
    if (e0 >= M) return;

    // broadcast-load up to 4 entry keys (valid keys are always < ~0ULL)
    unsigned long long k0 = (e0 + 0 < M) ? __ldg(keys + e0 + 0) : ~0ULL;
    unsigned long long k1 = (e0 + 1 < M) ? __ldg(keys + e0 + 1) : ~0ULL;
    unsigned long long k2 = (e0 + 2 < M) ? __ldg(keys + e0 + 2) : ~0ULL;
    unsigned long long k3 = (e0 + 3 < M) ? __ldg(keys + e0 + 3) : ~0ULL;

    int r0 = 0, r1 = 0, r2 = 0, r3 = 0;
    #pragma unroll 4
    for (int j = lane; j < M; j += 32) {
        unsigned long long kj = __ldg(keys + j);
        r0 += (kj < k0);
        r1 += (kj < k1);
        r2 += (kj < k2);
        r3 += (kj < k3);
    }
    #pragma unroll
    for (int o = 16; o; o >>= 1) {
        r0 += __shfl_xor_sync(0xffffffffu, r0, o);
        r1 += __shfl_xor_sync(0xffffffffu, r1, o);
        r2 += __shfl_xor_sync(0xffffffffu, r2, o);
        r3 += __shfl_xor_sync(0xffffffffu, r3, o);
    }

    if (lane == 0) {
        unsigned long long ks[4] = {k0, k1, k2, k3};
        int rs[4] = {r0, r1, r2, r3};
        #pragma unroll
        for (int i = 0; i < 4; ++i) {
            if (e0 + i < M && rs[i] < MAX_DET) {
                int idx = (int)(ks[i] & 1023ULL);
                int g = img * NP + idx;
                float4 v = g_boxes[g];
                int base = img * MAX_DET + rs[i];
                boxes_out[base * 4 + 0] = v.x;
                boxes_out[base * 4 + 1] = v.y;
                boxes_out[base * 4 + 2] = v.z;
                boxes_out[base * 4 + 3] = v.w;
                scores_out[base] = g_scores[g];
                labels_out[base] = (float)g_labels[g];
            }
        }
    }
}

// ---------------- launch ----------------
extern "C" void kernel_launch(void* const* d_in, const int* in_sizes, int n_in,
                              void* d_out, int out_size) {
    const float* class_logits  = (const float*)d_in[0];
    const float* bbox_deltas   = (const float*)d_in[1];
    const float* roi_proposals = (const float*)d_in[2];
    const int*   image_sizes   = (const int*)d_in[3];
    float* out = (float*)d_out;

    // A: one warp per PW proposals -> 2048 warps -> 256 CTAs of 256 threads
    int warpsA  = (NB * NP) / PW;
    int blocksA = (warpsA * 32) / 256;
    score_decode_kernel<<<blocksA, 256>>>(class_logits, bbox_deltas,
                                          roi_proposals, image_sizes);

    int nmsWarps = NB * 90;
    int nmsBlocks = (nmsWarps * 32 + 255) / 256;
    nms_class_kernel<<<nmsBlocks, 256>>>();

    topk_rank_kernel<<<NB * C_PARTS, 256>>>(out);
}

// round 17
// speedup vs baseline: 1.3330x; 1.0778x over previous
#include <cuda_runtime.h>
#include <float.h>
#include <math.h>

#define NB 16
#define NP 1024
#define NC 91
#define MAX_DET 100
#define SCORE_THRESH 0.05f
#define NMS_THRESH 0.5f
#define BBOX_CLIP 4.135166556742356f  /* log(1000/16) */
#define BK 128                        /* bucket capacity per (image,class) */
#define LOG2E 1.4426950408889634f
#define LN2   0.6931471805599453f

#define PW 8                          /* proposals per warp in kernel A */
#define C_PARTS 32                    /* 32 entries per part-CTA */

// ---------------- scratch (no allocations allowed) ----------------
__device__ float  g_scores[NB * NP];
__device__ int    g_labels[NB * NP];           // 0 if invalid, else 1..90
__device__ float4 g_boxes[NB * NP];

__device__ int    g_bcnt[NB * 91];             // bucket counts   (reset by B owner-warps)
__device__ float4 g_bbox[NB * 91 * BK];        // bucket boxes (raw clipped)
__device__ float  g_bsc [NB * 91 * BK];        // bucket scores
__device__ int    g_bidx[NB * 91 * BK];        // bucket original idx (0..1023)
__device__ int    g_maxc[NB];                  // per-image max coord (reset by C, after sync)
__device__ int    g_M[NB];                     // kept count per image (reset by A)
__device__ unsigned long long g_klist[NB * NP];// kept keys per image (contiguous)

// monotone injective float <-> ordinal-uint maps
__device__ __forceinline__ unsigned f2ord(float x) {
    unsigned u = __float_as_uint(x);
    return (u & 0x80000000u) ? ~u : (u | 0x80000000u);
}
__device__ __forceinline__ float ord2f(unsigned u) {
    return __uint_as_float((u & 0x80000000u) ? (u ^ 0x80000000u) : ~u);
}

// e^x for x <= BBOX_CLIP, pure FMA/ALU pipes (no MUFU). Max rel err ~5e-9 + rounding.
__device__ __forceinline__ float exp_poly(float x) {
    float y = x * LOG2E;
    y = fmaxf(y, -126.0f);
    float r = rintf(y);
    float f = y - r;
    float t = f * LN2;
    float p = 1.9841270114e-4f;
    p = fmaf(p, t, 1.3888888961e-3f);
    p = fmaf(p, t, 8.3333337680e-3f);
    p = fmaf(p, t, 4.1666667908e-2f);
    p = fmaf(p, t, 1.6666667163e-1f);
    p = fmaf(p, t, 5.0000000000e-1f);
    p = fmaf(p, t, 1.0f);
    p = fmaf(p, t, 1.0f);
    int n = (int)r;
    return __uint_as_float((unsigned)(n + 127) << 23) * p;
}

// ---------------- Kernel A: softmax-max/argmax + decode + clip + bucket ------
// One warp per PW=8 proposals. CTA = 64 props of ONE image. 2048 warps total.
__global__ __launch_bounds__(256) void score_decode_kernel(
        const float* __restrict__ logits,
        const float* __restrict__ deltas,
        const float* __restrict__ props,
        const int*   __restrict__ imsz) {
    __shared__ unsigned s_mc[8];

    if (blockIdx.x == 0 && threadIdx.x < NB) g_M[threadIdx.x] = 0;

    const int warpid = (blockIdx.x * blockDim.x + threadIdx.x) >> 5;
    const int warp   = threadIdx.x >> 5;
    const int lane   = threadIdx.x & 31;
    const int pa     = warpid * PW;
    const int b      = pa >> 10;

    float4 pr;
    int ih = 0, iw = 0;
    const int myP = pa + lane;
    if (lane < PW) {
        pr = *reinterpret_cast<const float4*>(props + (size_t)myP * 4);
        ih = imsz[b * 2 + 0];
        iw = imsz[b * 2 + 1];
    }

    const bool has2 = (lane < NC - 64);
    float L0[PW], L1[PW], L2[PW];
    #pragma unroll
    for (int i = 0; i < PW; ++i) {
        const float* r = logits + (size_t)(pa + i) * NC;
        L0[i] = r[lane];
        L1[i] = r[lane + 32];
        L2[i] = has2 ? r[lane + 64] : -FLT_MAX;
    }

    unsigned um[PW]; int im[PW];
    #pragma unroll
    for (int i = 0; i < PW; ++i) {
        unsigned u0 = f2ord(L0[i]); int ii = lane;
        unsigned u = f2ord(L1[i]); if (u > u0) { u0 = u; ii = lane + 32; }
        u = f2ord(L2[i]);          if (u > u0) { u0 = u; ii = lane + 64; }
        um[i] = u0; im[i] = ii;
    }

    unsigned uM[PW]; int lab[PW]; float mv[PW];
    #pragma unroll
    for (int i = 0; i < PW; ++i) uM[i] = __reduce_max_sync(0xffffffffu, um[i]);
    #pragma unroll
    for (int i = 0; i < PW; ++i)
        lab[i] = (int)__reduce_min_sync(0xffffffffu,
                    (um[i] == uM[i]) ? (unsigned)im[i] : 0x7fffffffu);
    #pragma unroll
    for (int i = 0; i < PW; ++i) mv[i] = ord2f(uM[i]);

    float s[PW];
    #pragma unroll
    for (int i = 0; i < PW; ++i)
        s[i] = exp_poly(L0[i] - mv[i]) + exp_poly(L1[i] - mv[i]) +
               (has2 ? exp_poly(L2[i] - mv[i]) : 0.0f);
    #pragma unroll
    for (int o = 16; o; o >>= 1) {
        #pragma unroll
        for (int i = 0; i < PW; ++i)
            s[i] += __shfl_xor_sync(0xffffffffu, s[i], o);
    }

    float mc = 0.0f;
    if (lane < PW) {
        float ssum = s[0]; int label = lab[0];
        #pragma unroll
        for (int i = 1; i < PW; ++i)
            if (lane == i) { ssum = s[i]; label = lab[i]; }
        float score = 1.0f / ssum;
        int   valid = (label > 0) && (score > SCORE_THRESH);

        float x1 = pr.x, y1 = pr.y, x2 = pr.z, y2 = pr.w;
        float w = x2 - x1, h = y2 - y1;
        float cx = x1 + 0.5f * w, cy = y1 + 0.5f * h;

        const float* dd = deltas + (size_t)myP * (NC * 4) + 4 * label;
        float dx = dd[0], dy = dd[1];
        float dw = fminf(dd[2], BBOX_CLIP), dh = fminf(dd[3], BBOX_CLIP);
        float pcx = dx * w + cx, pcy = dy * h + cy;
        float pw = exp_poly(dw) * w, ph = exp_poly(dh) * h;
        float bx1 = pcx - 0.5f * pw, by1 = pcy - 0.5f * ph;
        float bx2 = pcx + 0.5f * pw, by2 = pcy + 0.5f * ph;

        float hb = (float)ih;
        float wb = (float)iw;
        bx1 = fminf(fmaxf(bx1, 0.0f), wb);
        by1 = fminf(fmaxf(by1, 0.0f), hb);
        bx2 = fminf(fmaxf(bx2, 0.0f), wb);
        by2 = fminf(fmaxf(by2, 0.0f), hb);

        g_boxes[myP]  = make_float4(bx1, by1, bx2, by2);
        g_scores[myP] = score;
        g_labels[myP] = valid ? label : 0;

        if (valid) {
            mc = fmaxf(fmaxf(bx1, by1), fmaxf(bx2, by2));
            int bc = b * 91 + label;
            int p2 = atomicAdd(&g_bcnt[bc], 1);
            if (p2 < BK) {
                int slot = bc * BK + p2;
                g_bbox[slot] = make_float4(bx1, by1, bx2, by2);
                g_bsc[slot]  = score;
                g_bidx[slot] = myP - b * NP;
            }
        }
    }

    unsigned mu = __reduce_max_sync(0xffffffffu, __float_as_uint(mc));
    if (lane == 0) s_mc[warp] = mu;
    __syncthreads();
    if (threadIdx.x == 0) {
        unsigned m = s_mc[0];
        #pragma unroll
        for (int i = 1; i < 8; ++i) m = m > s_mc[i] ? m : s_mc[i];
        atomicMax(&g_maxc[b], (int)m);
    }
}

// ---------------- Kernel B: NMS, one warp per (image, class), registers only ----
// PDL: launched early; waits for A via cudaGridDependencySynchronize().
__global__ __launch_bounds__(256) void nms_class_kernel() {
    int gwarp = (blockIdx.x * blockDim.x + threadIdx.x) >> 5;
    int lane  = threadIdx.x & 31;
    int b = gwarp / 90;
    int c = 1 + gwarp % 90;
    int bc = b * 91 + c;

#if __CUDA_ARCH__ >= 900
    cudaGridDependencySynchronize();   // A's writes now visible
#endif
    if (gwarp >= NB * 90) return;

    int n = g_bcnt[bc];
    __syncwarp();
    if (lane == 0 && n != 0) g_bcnt[bc] = 0;   // reset for next replay
    if (n > BK) n = BK;
    if (n == 0) return;

    float K   = __int_as_float(g_maxc[b]) + 1.0f;
    float off = (float)c * K;    // label * (max_coord + 1), reference FP order

    float4 bxs[4]; float scs[4]; int idxs[4];
    unsigned alive = 0;
    #pragma unroll
    for (int j = 0; j < 4; ++j) {
        int e = j * 32 + lane;
        if (e < n) {
            float4 v = g_bbox[bc * BK + e];
            bxs[j] = make_float4(v.x + off, v.y + off, v.z + off, v.w + off);
            scs[j] = g_bsc[bc * BK + e];
            idxs[j] = g_bidx[bc * BK + e];
            alive |= (1u << j);
        } else {
            bxs[j] = make_float4(0.f, 0.f, 0.f, 0.f);
            scs[j] = 0.f; idxs[j] = 0;
        }
    }

    unsigned keptm = 0;
    while (true) {
        unsigned long long best = ~0ULL;
        #pragma unroll
        for (int j = 0; j < 4; ++j) {
            if (alive & (1u << j)) {
                unsigned long long k =
                    ((unsigned long long)(~__float_as_uint(scs[j])) << 20) |
                    ((unsigned long long)(unsigned)idxs[j] << 10) |
                    (unsigned long long)(unsigned)(j * 32 + lane);
                if (k < best) best = k;
            }
        }
        #pragma unroll
        for (int o = 16; o; o >>= 1) {
            unsigned long long ob = __shfl_xor_sync(0xffffffffu, best, o);
            if (ob < best) best = ob;
        }
        if (best == ~0ULL) break;

        int e   = (int)(best & 1023ULL);
        int js  = e >> 5;
        int src = e & 31;
        float4 own = (js == 0) ? bxs[0] : (js == 1) ? bxs[1] : (js == 2) ? bxs[2] : bxs[3];
        float4 A;
        A.x = __shfl_sync(0xffffffffu, own.x, src);
        A.y = __shfl_sync(0xffffffffu, own.y, src);
        A.z = __shfl_sync(0xffffffffu, own.z, src);
        A.w = __shfl_sync(0xffffffffu, own.w, src);
        if (lane == src) {
            alive &= ~(1u << js);
            keptm |= (1u << js);
        }
        float areaA = (A.z - A.x) * (A.w - A.y);

        #pragma unroll
        for (int j = 0; j < 4; ++j) {
            if (alive & (1u << j)) {
                float4 Bx = bxs[j];
                float areaB = (Bx.z - Bx.x) * (Bx.w - Bx.y);
                float ltx = fmaxf(A.x, Bx.x), lty = fmaxf(A.y, Bx.y);
                float rbx = fminf(A.z, Bx.z), rby = fminf(A.w, Bx.w);
                float wx = fmaxf(rbx - ltx, 0.0f), wy = fmaxf(rby - lty, 0.0f);
                float inter = wx * wy;
                float iou = inter / (areaA + areaB - inter + 1e-9f);
                if (iou > NMS_THRESH) alive &= ~(1u << j);
            }
        }
    }

    // single aggregated atomic per warp, ballot-prefixed positions
    int pref[4];
    int kc = 0;
    #pragma unroll
    for (int j = 0; j < 4; ++j) {
        bool kept = (keptm >> j) & 1u;
        unsigned bal = __ballot_sync(0xffffffffu, kept);
        pref[j] = kc + __popc(bal & ((1u << lane) - 1u));
        kc += __popc(bal);
    }
    int basep = 0;
    if (lane == 0 && kc > 0) basep = atomicAdd(&g_M[b], kc);
    basep = __shfl_sync(0xffffffffu, basep, 0);
    #pragma unroll
    for (int j = 0; j < 4; ++j) {
        if ((keptm >> j) & 1u) {
            g_klist[b * NP + basep + pref[j]] =
                ((unsigned long long)(~__float_as_uint(scs[j])) << 10) |
                (unsigned long long)(unsigned)idxs[j];
        }
    }
}

// ---------------- Kernel C: top-100 rank counting, 4 entries per warp --------
// PDL: launched early; waits for B via cudaGridDependencySynchronize().
__global__ __launch_bounds__(256) void topk_rank_kernel(float* __restrict__ out) {
    const int img  = blockIdx.x / C_PARTS;
    const int part = blockIdx.x % C_PARTS;
    const int t    = threadIdx.x;
    const int warp = t >> 5;
    const int lane = t & 31;

#if __CUDA_ARCH__ >= 900
    cudaGridDependencySynchronize();   // B's writes now visible; B done with g_maxc
#endif
    // reset g_maxc only AFTER the sync (B reads it; with PDL we may be resident early)
    if (blockIdx.x == 0 && t < NB) g_maxc[t] = 0;

    int M = g_M[img];
    if (M > NP) M = NP;

    float* boxes_out  = out;
    float* scores_out = out + NB * MAX_DET * 4;
    float* labels_out = out + NB * MAX_DET * 5;

    const int filled = M < MAX_DET ? M : MAX_DET;
    if (part == 0 && t >= filled && t < MAX_DET) {
        int base = img * MAX_DET + t;
        boxes_out[base * 4 + 0] = 0.0f;
        boxes_out[base * 4 + 1] = 0.0f;
        boxes_out[base * 4 + 2] = 0.0f;
        boxes_out[base * 4 + 3] = 0.0f;
        scores_out[base] = 0.0f;
        labels_out[base] = -1.0f;
    }

    const unsigned long long* keys = g_klist + (size_t)img * NP;
    const int e0 = part * 32 + warp * 4;
    if (e0 >= M) return;

    unsigned long long k0 = (e0 + 0 < M) ? __ldg(keys + e0 + 0) : ~0ULL;
    unsigned long long k1 = (e0 + 1 < M) ? __ldg(keys + e0 + 1) : ~0ULL;
    unsigned long long k2 = (e0 + 2 < M) ? __ldg(keys + e0 + 2) : ~0ULL;
    unsigned long long k3 = (e0 + 3 < M) ? __ldg(keys + e0 + 3) : ~0ULL;

    int r0 = 0, r1 = 0, r2 = 0, r3 = 0;
    #pragma unroll 4
    for (int j = lane; j < M; j += 32) {
        unsigned long long kj = __ldg(keys + j);
        r0 += (kj < k0);
        r1 += (kj < k1);
        r2 += (kj < k2);
        r3 += (kj < k3);
    }
    #pragma unroll
    for (int o = 16; o; o >>= 1) {
        r0 += __shfl_xor_sync(0xffffffffu, r0, o);
        r1 += __shfl_xor_sync(0xffffffffu, r1, o);
        r2 += __shfl_xor_sync(0xffffffffu, r2, o);
        r3 += __shfl_xor_sync(0xffffffffu, r3, o);
    }

    if (lane == 0) {
        unsigned long long ks[4] = {k0, k1, k2, k3};
        int rs[4] = {r0, r1, r2, r3};
        #pragma unroll
        for (int i = 0; i < 4; ++i) {
            if (e0 + i < M && rs[i] < MAX_DET) {
                int idx = (int)(ks[i] & 1023ULL);
                int g = img * NP + idx;
                float4 v = g_boxes[g];
                int base = img * MAX_DET + rs[i];
                boxes_out[base * 4 + 0] = v.x;
                boxes_out[base * 4 + 1] = v.y;
                boxes_out[base * 4 + 2] = v.z;
                boxes_out[base * 4 + 3] = v.w;
                scores_out[base] = g_scores[g];
                labels_out[base] = (float)g_labels[g];
            }
        }
    }
}

// ---------------- launch ----------------
extern "C" void kernel_launch(void* const* d_in, const int* in_sizes, int n_in,
                              void* d_out, int out_size) {
    const float* class_logits  = (const float*)d_in[0];
    const float* bbox_deltas   = (const float*)d_in[1];
    const float* roi_proposals = (const float*)d_in[2];
    const int*   image_sizes   = (const int*)d_in[3];
    float* out = (float*)d_out;

    // A: one warp per PW proposals -> 2048 warps -> 256 CTAs of 256 threads
    int warpsA  = (NB * NP) / PW;
    int blocksA = (warpsA * 32) / 256;
    score_decode_kernel<<<blocksA, 256>>>(class_logits, bbox_deltas,
                                          roi_proposals, image_sizes);

    // B and C launched with programmatic dependent launch (overlap ramps)
    cudaLaunchAttribute attr[1];
    attr[0].id = cudaLaunchAttributeProgrammaticStreamSerialization;
    attr[0].val.programmaticStreamSerializationAllowed = 1;

    {
        int nmsWarps = NB * 90;
        int nmsBlocks = (nmsWarps * 32 + 255) / 256;
        cudaLaunchConfig_t cfg = {};
        cfg.gridDim  = dim3((unsigned)nmsBlocks, 1, 1);
        cfg.blockDim = dim3(256, 1, 1);
        cfg.dynamicSmemBytes = 0;
        cfg.stream = 0;
        cfg.attrs = attr;
        cfg.numAttrs = 1;
        cudaLaunchKernelEx(&cfg, nms_class_kernel);
    }
    {
        cudaLaunchConfig_t cfg = {};
        cfg.gridDim  = dim3(NB * C_PARTS, 1, 1);
        cfg.blockDim = dim3(256, 1, 1);
        cfg.dynamicSmemBytes = 0;
        cfg.stream = 0;
        cfg.attrs = attr;
        cfg.numAttrs = 1;
        cudaLaunchKernelEx(&cfg, topk_rank_kernel, out);
    }
}